// round 1
// baseline (speedup 1.0000x reference)
#include <cuda_runtime.h>
#include <cuda_bf16.h>
#include <cstdint>

// LightGCN: deg = clamp(segsum(w by dst),1); norm = deg^-1/2
// repeat 2x: h = segsum((h*norm)[src]*w by dst) * norm
// out = mean(h0,h1,h2)

#define NN   100000
#define DIMV 16          // 64 floats = 16 float4 per node
#define EE   1600000

// Scratch (allocation-free rule: __device__ globals)
__device__ float g_deg[NN];
__device__ float g_norm[NN];
__device__ float4 g_hn [(size_t)NN * DIMV];   // (h * norm), layer input
__device__ float4 g_acc[(size_t)NN * DIMV];   // scatter accumulator

static __device__ __forceinline__ void red_add_v4(float* addr, float4 v) {
    asm volatile("red.global.add.v4.f32 [%0], {%1, %2, %3, %4};"
                 :: "l"(addr), "f"(v.x), "f"(v.y), "f"(v.z), "f"(v.w)
                 : "memory");
}

__global__ void k_deg_zero(int n) {
    int i = blockIdx.x * blockDim.x + threadIdx.x;
    if (i < n) g_deg[i] = 0.0f;
}

__global__ void k_deg_add(const float* __restrict__ w,
                          const int* __restrict__ dst, int e) {
    int i = blockIdx.x * blockDim.x + threadIdx.x;
    if (i < e) atomicAdd(&g_deg[dst[i]], w[i]);
}

__global__ void k_norm(int n) {
    int i = blockIdx.x * blockDim.x + threadIdx.x;
    if (i < n) g_norm[i] = rsqrtf(fmaxf(g_deg[i], 1.0f));
}

// out = h (first term of the mean); g_hn = h*norm; g_acc = 0
__global__ void k_prep(const float4* __restrict__ h, float4* __restrict__ out, int n4) {
    int i = blockIdx.x * blockDim.x + threadIdx.x;
    if (i >= n4) return;
    int node = i >> 4;                 // 16 float4 per node
    float nm = g_norm[node];
    float4 v = h[i];
    out[i] = v;
    g_hn[i]  = make_float4(v.x * nm, v.y * nm, v.z * nm, v.w * nm);
    g_acc[i] = make_float4(0.f, 0.f, 0.f, 0.f);
}

// 16 threads per edge, each owns one float4 chunk of the 64-dim row.
__global__ void k_scatter(const int* __restrict__ src,
                          const int* __restrict__ dst,
                          const float* __restrict__ w, int e) {
    int t = blockIdx.x * blockDim.x + threadIdx.x;
    int edge = t >> 4;
    int c = t & 15;
    if (edge >= e) return;
    int   s  = __ldg(&src[edge]);
    int   d  = __ldg(&dst[edge]);
    float wt = __ldg(&w[edge]);
    float4 v = g_hn[(size_t)s * DIMV + c];
    float4 m = make_float4(v.x * wt, v.y * wt, v.z * wt, v.w * wt);
    red_add_v4(reinterpret_cast<float*>(&g_acc[(size_t)d * DIMV + c]), m);
}

// h1 = acc*norm; out += h1; g_hn = h1*norm (next layer input); acc = 0
__global__ void k_mid(float4* __restrict__ out, int n4) {
    int i = blockIdx.x * blockDim.x + threadIdx.x;
    if (i >= n4) return;
    int node = i >> 4;
    float nm = g_norm[node];
    float4 a = g_acc[i];
    float4 h1 = make_float4(a.x * nm, a.y * nm, a.z * nm, a.w * nm);
    float4 o = out[i];
    out[i] = make_float4(o.x + h1.x, o.y + h1.y, o.z + h1.z, o.w + h1.w);
    g_hn[i]  = make_float4(h1.x * nm, h1.y * nm, h1.z * nm, h1.w * nm);
    g_acc[i] = make_float4(0.f, 0.f, 0.f, 0.f);
}

// out = (out + acc*norm) / 3
__global__ void k_final(float4* __restrict__ out, int n4) {
    int i = blockIdx.x * blockDim.x + threadIdx.x;
    if (i >= n4) return;
    int node = i >> 4;
    float nm = g_norm[node];
    float4 a = g_acc[i];
    float4 o = out[i];
    const float third = 1.0f / 3.0f;
    out[i] = make_float4((o.x + a.x * nm) * third,
                         (o.y + a.y * nm) * third,
                         (o.z + a.z * nm) * third,
                         (o.w + a.w * nm) * third);
}

extern "C" void kernel_launch(void* const* d_in, const int* in_sizes, int n_in,
                              void* d_out, int out_size) {
    const float* h   = (const float*)d_in[0];
    const float* w   = (const float*)d_in[1];
    const int*   src = (const int*)d_in[2];
    const int*   dst = (const int*)d_in[3];
    float* out = (float*)d_out;

    const int N  = in_sizes[0] / 64;   // 100000
    const int E  = in_sizes[1];        // 1600000
    const int N4 = N * DIMV;           // float4 count
    const int B  = 256;

    // degree + norm
    k_deg_zero<<<(N + B - 1) / B, B>>>(N);
    k_deg_add<<<(E + B - 1) / B, B>>>(w, dst, E);
    k_norm<<<(N + B - 1) / B, B>>>(N);

    // layer 0 prep: out = h, hn = h*norm, acc = 0
    k_prep<<<(N4 + B - 1) / B, B>>>((const float4*)h, (float4*)out, N4);

    // layer 1
    {
        long long work = (long long)E * 16;
        k_scatter<<<(int)((work + B - 1) / B), B>>>(src, dst, w, E);
    }
    k_mid<<<(N4 + B - 1) / B, B>>>((float4*)out, N4);

    // layer 2
    {
        long long work = (long long)E * 16;
        k_scatter<<<(int)((work + B - 1) / B), B>>>(src, dst, w, E);
    }
    k_final<<<(N4 + B - 1) / B, B>>>((float4*)out, N4);
}

// round 3
// speedup vs baseline: 1.5930x; 1.5930x over previous
#include <cuda_runtime.h>
#include <cuda_bf16.h>
#include <cstdint>

// LightGCN via pull-based CSR gather (built per-launch; graph-capturable,
// allocation-free: all scratch in __device__ globals, referenced ONLY from
// device code — host code must never take their address).
//
// deg = clamp(segsum(w by dst), 1); norm = deg^-1/2
// repeat 2x: h = segsum((h*norm)[src] * w, by dst) * norm
// out = mean(h0, h1, h2)

#define NN    100000
#define EE    1600000

__device__ float  g_deg[NN];
__device__ int    g_cnt[NN];
__device__ float  g_norm[NN];
__device__ int    g_rowptr[NN + 1];
__device__ int    g_cursor[NN];
__device__ int    g_bsum[128];
__device__ float2 g_edge[EE];              // .x = __int_as_float(src), .y = w
__device__ float2 g_ha[(size_t)NN * 32];   // layer input  (h*norm)
__device__ float2 g_hb[(size_t)NN * 32];   // layer output (h*norm)

// ---------------- CSR build ----------------

__global__ void k_zero(int n) {
    int i = blockIdx.x * blockDim.x + threadIdx.x;
    if (i < n) { g_deg[i] = 0.0f; g_cnt[i] = 0; }
}

__global__ void k_hist(const float* __restrict__ w,
                       const int* __restrict__ dst, int e) {
    int i = blockIdx.x * blockDim.x + threadIdx.x;
    if (i >= e) return;
    int d = dst[i];
    atomicAdd(&g_deg[d], w[i]);
    atomicAdd(&g_cnt[d], 1);
}

// Pass A: per-block exclusive scan of g_cnt -> g_rowptr (block-local); totals -> g_bsum
__global__ void k_scanA(int n) {
    __shared__ int sh[32];
    int i = blockIdx.x * 1024 + threadIdx.x;
    int lane = threadIdx.x & 31, wid = threadIdx.x >> 5;
    int v = (i < n) ? g_cnt[i] : 0;
    int x = v;
    #pragma unroll
    for (int o = 1; o < 32; o <<= 1) {
        int y = __shfl_up_sync(0xffffffffu, x, o);
        if (lane >= o) x += y;
    }
    if (lane == 31) sh[wid] = x;
    __syncthreads();
    if (wid == 0) {
        int s = sh[lane];
        #pragma unroll
        for (int o = 1; o < 32; o <<= 1) {
            int y = __shfl_up_sync(0xffffffffu, s, o);
            if (lane >= o) s += y;
        }
        sh[lane] = s;
    }
    __syncthreads();
    int excl = x - v + (wid > 0 ? sh[wid - 1] : 0);
    if (i < n) g_rowptr[i] = excl;
    if (threadIdx.x == 1023) g_bsum[blockIdx.x] = excl + v;
}

// Pass B: single-block exclusive scan of block totals (nb <= 128)
__global__ void k_scanB(int nb) {
    __shared__ int sh[4];
    int t = threadIdx.x;           // 128 threads
    int lane = t & 31, wid = t >> 5;
    int v = (t < nb) ? g_bsum[t] : 0;
    int x = v;
    #pragma unroll
    for (int o = 1; o < 32; o <<= 1) {
        int y = __shfl_up_sync(0xffffffffu, x, o);
        if (lane >= o) x += y;
    }
    if (lane == 31) sh[wid] = x;
    __syncthreads();
    int add = 0;
    for (int k = 0; k < wid; k++) add += sh[k];
    g_bsum[t] = x - v + add;       // exclusive
}

// Pass C: finalize rowptr, init cursor, compute norm
__global__ void k_scanC(int n, int e) {
    int i = blockIdx.x * 1024 + threadIdx.x;
    if (i >= n) return;
    int r = g_rowptr[i] + g_bsum[blockIdx.x];
    g_rowptr[i] = r;
    g_cursor[i] = r;
    g_norm[i] = rsqrtf(fmaxf(g_deg[i], 1.0f));
    if (i == 0) g_rowptr[n] = e;
}

__global__ void k_fill(const int* __restrict__ src,
                       const int* __restrict__ dst,
                       const float* __restrict__ w, int e) {
    int i = blockIdx.x * blockDim.x + threadIdx.x;
    if (i >= e) return;
    int d = dst[i];
    int pos = atomicAdd(&g_cursor[d], 1);
    g_edge[pos] = make_float2(__int_as_float(src[i]), w[i]);
}

// ---------------- layer kernels ----------------

// out = h; g_ha = h * norm
__global__ void k_prep(const float4* __restrict__ h, float4* __restrict__ out, int n4) {
    int i = blockIdx.x * blockDim.x + threadIdx.x;
    if (i >= n4) return;
    int node = i >> 4;
    float nm = g_norm[node];
    float4 v = h[i];
    out[i] = v;
    reinterpret_cast<float4*>(g_ha)[i] =
        make_float4(v.x * nm, v.y * nm, v.z * nm, v.w * nm);
}

// Warp per node; lane owns dims [2*lane, 2*lane+1].
// LAYER=0: read g_ha; h1 = sum*norm; out += h1; g_hb = h1*norm
// LAYER=1: read g_hb; h2 = sum*norm; out = (out + h2) / 3
template <int LAYER>
__global__ void k_gather(float2* __restrict__ out, int n) {
    const float2* hin = (LAYER == 0) ? g_ha : g_hb;
    int warp = (blockIdx.x * blockDim.x + threadIdx.x) >> 5;
    int lane = threadIdx.x & 31;
    if (warp >= n) return;
    int beg = g_rowptr[warp];
    int end = g_rowptr[warp + 1];

    float ax = 0.f, ay = 0.f;
    int j = beg;
    for (; j + 4 <= end; j += 4) {
        float2 e0 = g_edge[j],   e1 = g_edge[j+1];
        float2 e2 = g_edge[j+2], e3 = g_edge[j+3];
        float2 v0 = hin[(size_t)__float_as_int(e0.x) * 32 + lane];
        float2 v1 = hin[(size_t)__float_as_int(e1.x) * 32 + lane];
        float2 v2 = hin[(size_t)__float_as_int(e2.x) * 32 + lane];
        float2 v3 = hin[(size_t)__float_as_int(e3.x) * 32 + lane];
        ax += v0.x * e0.y; ay += v0.y * e0.y;
        ax += v1.x * e1.y; ay += v1.y * e1.y;
        ax += v2.x * e2.y; ay += v2.y * e2.y;
        ax += v3.x * e3.y; ay += v3.y * e3.y;
    }
    for (; j < end; ++j) {
        float2 e = g_edge[j];
        float2 v = hin[(size_t)__float_as_int(e.x) * 32 + lane];
        ax += v.x * e.y; ay += v.y * e.y;
    }

    float nm = g_norm[warp];
    float hx = ax * nm, hy = ay * nm;
    size_t idx = (size_t)warp * 32 + lane;
    float2 o = out[idx];
    if (LAYER == 1) {
        const float third = 1.0f / 3.0f;
        out[idx] = make_float2((o.x + hx) * third, (o.y + hy) * third);
    } else {
        out[idx] = make_float2(o.x + hx, o.y + hy);
        g_hb[idx] = make_float2(hx * nm, hy * nm);
    }
}

extern "C" void kernel_launch(void* const* d_in, const int* in_sizes, int n_in,
                              void* d_out, int out_size) {
    const float* h   = (const float*)d_in[0];
    const float* w   = (const float*)d_in[1];
    const int*   src = (const int*)d_in[2];
    const int*   dst = (const int*)d_in[3];
    float* out = (float*)d_out;

    const int N  = in_sizes[0] / 64;   // 100000
    const int E  = in_sizes[1];        // 1600000
    const int N4 = N * 16;
    const int B  = 256;
    const int nb = (N + 1023) / 1024;  // 98

    // CSR build + norm
    k_zero <<<(N + B - 1) / B, B>>>(N);
    k_hist <<<(E + B - 1) / B, B>>>(w, dst, E);
    k_scanA<<<nb, 1024>>>(N);
    k_scanB<<<1, 128>>>(nb);
    k_scanC<<<nb, 1024>>>(N, E);
    k_fill <<<(E + B - 1) / B, B>>>(src, dst, w, E);

    // layer 0: out = h, ha = h*norm
    k_prep<<<(N4 + B - 1) / B, B>>>((const float4*)h, (float4*)out, N4);

    const int warpsPerBlock = B / 32;
    const int grid = (N + warpsPerBlock - 1) / warpsPerBlock;
    // layer 1: gather g_ha -> g_hb, out += h1
    k_gather<0><<<grid, B>>>((float2*)out, N);
    // layer 2: gather g_hb, out = (out + h2)/3
    k_gather<1><<<grid, B>>>((float2*)out, N);
}

// round 5
// speedup vs baseline: 1.6945x; 1.0637x over previous
#include <cuda_runtime.h>
#include <cuda_bf16.h>
#include <cuda_fp16.h>
#include <cstdint>

// LightGCN via pull-based CSR gather, fp16 intermediate embeddings.
// deg = clamp(segsum(w by dst), 1); norm = deg^-1/2
// repeat 2x: h = segsum((h*norm)[src] * w, by dst) * norm
// out = mean(h0, h1, h2)
//
// All scratch in __device__ globals (allocation-free); device globals are
// referenced only from device code.

#define NN    100000
#define EE    1600000

__device__ float   g_deg[NN];
__device__ int     g_cnt[NN];
__device__ float   g_norm[NN];
__device__ int     g_rowptr[NN + 1];
__device__ int     g_cursor[NN];
__device__ int     g_bsum[128];
__device__ float2  g_edge[EE];               // .x = __int_as_float(src), .y = w
__device__ __half2 g_ha[(size_t)NN * 32];    // layer-1 input (h0*norm), fp16
__device__ __half2 g_hb[(size_t)NN * 32];    // layer-2 input (h1*norm), fp16

// ---------------- CSR build ----------------

__global__ void k_zero(int n) {
    int i = blockIdx.x * blockDim.x + threadIdx.x;
    if (i < n) { g_deg[i] = 0.0f; g_cnt[i] = 0; }
}

__global__ void k_hist(const float* __restrict__ w,
                       const int* __restrict__ dst, int e) {
    int i = blockIdx.x * blockDim.x + threadIdx.x;
    if (i >= e) return;
    int d = dst[i];
    atomicAdd(&g_deg[d], w[i]);
    atomicAdd(&g_cnt[d], 1);
}

// Pass A: per-block exclusive scan of g_cnt -> g_rowptr (block-local); totals -> g_bsum
__global__ void k_scanA(int n) {
    __shared__ int sh[32];
    int i = blockIdx.x * 1024 + threadIdx.x;
    int lane = threadIdx.x & 31, wid = threadIdx.x >> 5;
    int v = (i < n) ? g_cnt[i] : 0;
    int x = v;
    #pragma unroll
    for (int o = 1; o < 32; o <<= 1) {
        int y = __shfl_up_sync(0xffffffffu, x, o);
        if (lane >= o) x += y;
    }
    if (lane == 31) sh[wid] = x;
    __syncthreads();
    if (wid == 0) {
        int s = sh[lane];
        #pragma unroll
        for (int o = 1; o < 32; o <<= 1) {
            int y = __shfl_up_sync(0xffffffffu, s, o);
            if (lane >= o) s += y;
        }
        sh[lane] = s;
    }
    __syncthreads();
    int excl = x - v + (wid > 0 ? sh[wid - 1] : 0);
    if (i < n) g_rowptr[i] = excl;
    if (threadIdx.x == 1023) g_bsum[blockIdx.x] = excl + v;
}

// Pass B+C+prep fused (1024 threads/block, nb blocks):
//  - each block computes its own prefix over g_bsum (<=128 entries, warp 0)
//  - finalize rowptr/cursor, compute norm (into smem)
//  - prep: out = h; g_ha = fp16(h * norm)
__global__ void k_scanC(const float4* __restrict__ h, float4* __restrict__ out,
                        int n, int e, int nb) {
    __shared__ float s_norm[1024];
    __shared__ int s_off;
    int t = threadIdx.x;
    int lane = t & 31;
    int base = blockIdx.x * 1024;

    // block offset = sum of g_bsum[0..blockIdx)
    if (t < 32) {
        int acc = 0;
        for (int k = lane; k < blockIdx.x; k += 32) acc += g_bsum[k];
        #pragma unroll
        for (int o = 16; o > 0; o >>= 1)
            acc += __shfl_down_sync(0xffffffffu, acc, o);
        if (lane == 0) s_off = acc;
    }
    __syncthreads();
    int off = s_off;

    int i = base + t;
    float nm = 0.0f;
    if (i < n) {
        int r = g_rowptr[i] + off;
        g_rowptr[i] = r;
        g_cursor[i] = r;
        nm = rsqrtf(fmaxf(g_deg[i], 1.0f));
        g_norm[i] = nm;
        if (i == 0) g_rowptr[n] = e;
    }
    s_norm[t] = nm;
    __syncthreads();

    // prep: this block's nodes [base, base+1024): 16 float4 each, coalesced
    #pragma unroll
    for (int k = 0; k < 16; k++) {
        int idx4 = base * 16 + t + k * 1024;   // global float4 index
        int node = idx4 >> 4;
        if (node >= n) break;
        float nrm = s_norm[node - base];
        float4 v = h[idx4];
        out[idx4] = v;
        g_ha[(size_t)idx4 * 2]     = __floats2half2_rn(v.x * nrm, v.y * nrm);
        g_ha[(size_t)idx4 * 2 + 1] = __floats2half2_rn(v.z * nrm, v.w * nrm);
    }
}

__global__ void k_fill(const int* __restrict__ src,
                       const int* __restrict__ dst,
                       const float* __restrict__ w, int e) {
    int i = blockIdx.x * blockDim.x + threadIdx.x;
    if (i >= e) return;
    int d = dst[i];
    int pos = atomicAdd(&g_cursor[d], 1);
    g_edge[pos] = make_float2(__int_as_float(src[i]), w[i]);
}

// ---------------- gather layers ----------------

// Warp per node; lane owns dims [2*lane, 2*lane+1] (one __half2).
// LAYER=0: read g_ha; h1 = sum*norm; out += h1; g_hb = fp16(h1*norm)
// LAYER=1: read g_hb; h2 = sum*norm; out = (out + h2) / 3
template <int LAYER>
__global__ void k_gather(float2* __restrict__ out, int n) {
    const __half2* hin = (LAYER == 0) ? g_ha : g_hb;
    int warp = (blockIdx.x * blockDim.x + threadIdx.x) >> 5;
    int lane = threadIdx.x & 31;
    if (warp >= n) return;
    int beg = g_rowptr[warp];
    int end = g_rowptr[warp + 1];

    float ax = 0.f, ay = 0.f;
    int j = beg;
    for (; j + 4 <= end; j += 4) {
        float2 e0 = g_edge[j],   e1 = g_edge[j+1];
        float2 e2 = g_edge[j+2], e3 = g_edge[j+3];
        float2 v0 = __half22float2(hin[(size_t)__float_as_int(e0.x) * 32 + lane]);
        float2 v1 = __half22float2(hin[(size_t)__float_as_int(e1.x) * 32 + lane]);
        float2 v2 = __half22float2(hin[(size_t)__float_as_int(e2.x) * 32 + lane]);
        float2 v3 = __half22float2(hin[(size_t)__float_as_int(e3.x) * 32 + lane]);
        ax += v0.x * e0.y; ay += v0.y * e0.y;
        ax += v1.x * e1.y; ay += v1.y * e1.y;
        ax += v2.x * e2.y; ay += v2.y * e2.y;
        ax += v3.x * e3.y; ay += v3.y * e3.y;
    }
    for (; j < end; ++j) {
        float2 e = g_edge[j];
        float2 v = __half22float2(hin[(size_t)__float_as_int(e.x) * 32 + lane]);
        ax += v.x * e.y; ay += v.y * e.y;
    }

    float nm = g_norm[warp];
    float hx = ax * nm, hy = ay * nm;
    size_t idx = (size_t)warp * 32 + lane;
    float2 o = out[idx];
    if (LAYER == 1) {
        const float third = 1.0f / 3.0f;
        out[idx] = make_float2((o.x + hx) * third, (o.y + hy) * third);
    } else {
        out[idx] = make_float2(o.x + hx, o.y + hy);
        g_hb[idx] = __floats2half2_rn(hx * nm, hy * nm);
    }
}

extern "C" void kernel_launch(void* const* d_in, const int* in_sizes, int n_in,
                              void* d_out, int out_size) {
    const float* h   = (const float*)d_in[0];
    const float* w   = (const float*)d_in[1];
    const int*   src = (const int*)d_in[2];
    const int*   dst = (const int*)d_in[3];
    float* out = (float*)d_out;

    const int N  = in_sizes[0] / 64;   // 100000
    const int E  = in_sizes[1];        // 1600000
    const int B  = 256;
    const int nb = (N + 1023) / 1024;  // 98

    k_zero <<<(N + B - 1) / B, B>>>(N);
    k_hist <<<(E + B - 1) / B, B>>>(w, dst, E);
    k_scanA<<<nb, 1024>>>(N);
    k_scanC<<<nb, 1024>>>((const float4*)h, (float4*)out, N, E, nb);
    k_fill <<<(E + B - 1) / B, B>>>(src, dst, w, E);

    const int warpsPerBlock = B / 32;
    const int grid = (N + warpsPerBlock - 1) / warpsPerBlock;
    k_gather<0><<<grid, B>>>((float2*)out, N);
    k_gather<1><<<grid, B>>>((float2*)out, N);
}